// round 2
// baseline (speedup 1.0000x reference)
#include <cuda_runtime.h>

// ReceptiveFieldLayer: J=4, R=10, pad=3  (from LAYER_INFO)
// out[b,c,i,j] = relu( max over x in [ceil((i-6)/4), floor((i+3)/4)],
//                               y in [ceil((j-6)/4), floor((j+3)/4)]
//                      of in[b, x, y, c] )   for c in {0,1,2}
//
// Input : [16, 256, 256, 64] f32 (NHWC, C innermost)
// Output: [16, 3, 1024, 1024] f32
//
// Tile: 32x128 output per CTA. Feature patch needed: rows fq-1..fq+8 (10),
// cols gq-1..gq+32 (34), 3 channels -> 4080 B shared.
// Each thread owns a 4x4 output block whose dependency is a 3x3 shared patch.

#define TILE_H 32
#define TILE_W 128
#define SH_H 10
#define SH_W 34
#define NPOS (SH_H * SH_W)   // 340

__global__ __launch_bounds__(256)
void rf_scatter_max_kernel(const float* __restrict__ in, float* __restrict__ out) {
    __shared__ float sh[3][SH_H][SH_W];

    const int b  = blockIdx.z;
    const int i0 = blockIdx.y * TILE_H;   // output row base (multiple of 32)
    const int j0 = blockIdx.x * TILE_W;   // output col base (multiple of 128)
    const int fq = i0 >> 2;               // feature row base quotient
    const int gq = j0 >> 2;

    const int tid = threadIdx.x;

    // ---- Load 3-channel feature patch (zero-padded outside [0,256)) ----
    for (int pos = tid; pos < NPOS; pos += 256) {
        int sx = pos / SH_W;
        int sy = pos - sx * SH_W;
        int fx = fq - 1 + sx;
        int fy = gq - 1 + sy;
        float x = 0.f, y = 0.f, z = 0.f;
        if ((unsigned)fx < 256u && (unsigned)fy < 256u) {
            const float4 v = __ldg(reinterpret_cast<const float4*>(
                in + ((((size_t)b * 256 + fx) * 256 + fy) << 6)));
            x = v.x; y = v.y; z = v.z;
        }
        sh[0][sx][sy] = x;
        sh[1][sx][sy] = y;
        sh[2][sx][sy] = z;
    }
    __syncthreads();

    // ---- Each thread: 4x4 output block from a 3x3 shared patch ----
    const int q  = tid & 31;   // col group: output cols j0+4q .. +3, shared cols q..q+2
    const int rg = tid >> 5;   // row group: output rows i0+4rg .. +3, shared rows rg..rg+2

    #pragma unroll
    for (int ch = 0; ch < 3; ch++) {
        float a00 = sh[ch][rg    ][q], a01 = sh[ch][rg    ][q + 1], a02 = sh[ch][rg    ][q + 2];
        float a10 = sh[ch][rg + 1][q], a11 = sh[ch][rg + 1][q + 1], a12 = sh[ch][rg + 1][q + 2];
        float a20 = sh[ch][rg + 2][q], a21 = sh[ch][rg + 2][q + 1], a22 = sh[ch][rg + 2][q + 2];

        // column maxes per shared row: taps {t,t+1}, {t+1,t+2}, {t,t+1,t+2}
        float c0a = fmaxf(a00, a01), c0b = fmaxf(a01, a02), c0c = fmaxf(c0a, a02);
        float c1a = fmaxf(a10, a11), c1b = fmaxf(a11, a12), c1c = fmaxf(c1a, a12);
        float c2a = fmaxf(a20, a21), c2b = fmaxf(a21, a22), c2c = fmaxf(c2a, a22);

        // row combos (relu folded via fmax with 0)
        // row k=0 -> shared rows {rg, rg+1}; k=1,2 -> {rg..rg+2}; k=3 -> {rg+1, rg+2}
        float r01_a  = fmaxf(fmaxf(c0a, c1a), 0.f);
        float r01_c  = fmaxf(fmaxf(c0c, c1c), 0.f);
        float r01_b  = fmaxf(fmaxf(c0b, c1b), 0.f);
        float r012_a = fmaxf(r01_a, c2a);
        float r012_c = fmaxf(r01_c, c2c);
        float r012_b = fmaxf(r01_b, c2b);
        float r12_a  = fmaxf(fmaxf(c1a, c2a), 0.f);
        float r12_c  = fmaxf(fmaxf(c1c, c2c), 0.f);
        float r12_b  = fmaxf(fmaxf(c1b, c2b), 0.f);

        // col k'=0 -> taps {q,q+1} (a); k'=1,2 -> {q..q+2} (c); k'=3 -> {q+1,q+2} (b)
        float4 v0 = make_float4(r01_a,  r01_c,  r01_c,  r01_b);
        float4 v1 = make_float4(r012_a, r012_c, r012_c, r012_b);
        float4 v3 = make_float4(r12_a,  r12_c,  r12_c,  r12_b);

        size_t base = ((((size_t)b * 3 + ch) * 1024) + (size_t)(i0 + rg * 4)) * 1024
                      + (size_t)(j0 + q * 4);
        float4* o = reinterpret_cast<float4*>(out + base);
        __stcs(o,        v0);
        __stcs(o +  256, v1);   // +1024 floats = +256 float4
        __stcs(o +  512, v1);
        __stcs(o +  768, v3);
    }
}

extern "C" void kernel_launch(void* const* d_in, const int* in_sizes, int n_in,
                              void* d_out, int out_size) {
    const float* in = (const float*)d_in[0];
    float* out = (float*)d_out;
    dim3 grid(1024 / TILE_W, 1024 / TILE_H, 16);   // (8, 32, 16)
    rf_scatter_max_kernel<<<grid, 256>>>(in, out);
}